// round 3
// baseline (speedup 1.0000x reference)
#include <cuda_runtime.h>
#include <cuda_bf16.h>
#include <cstdint>

#define N_NODES 20000
#define N_EDGES 200000
#define FEAT    128
#define NB      8
#define SI      16
#define SO      16
#define NREL    230
#define WROW    (NB*SI*SO)       // 2048 floats per relation
#define NSUB    32               // sub-counters per relation
#define NCNT    (NREL*NSUB)      // 7360
#define EPW     32               // edges per warp (divides N_EDGES exactly)
#define NWARPS  (N_EDGES/EPW)    // 6250

// ---------------- packed f32x2 helpers (Blackwell sm_103a) --------------------
#define PACK_F32X2(out, lo, hi) \
    asm("mov.b64 %0, {%1, %2};" : "=l"(out) : "f"(lo), "f"(hi))
#define UNPACK_F32X2(lo, hi, in) \
    asm("mov.b64 {%0, %1}, %2;" : "=f"(lo), "=f"(hi) : "l"(in))
#define FMA_F32X2(d, a, b, c) \
    asm("fma.rn.f32x2 %0, %1, %2, %3;" : "=l"(d) : "l"(a), "l"(b), "l"(c))

// ---------------- scratch (device globals) -------------------------------------
__device__ float g_agg[(size_t)N_NODES * FEAT];      // 10.24 MB
__device__ int   g_counts[NCNT];
__device__ int   g_cursor[NCNT];
__device__ int4  g_edge[N_EDGES];                    // sorted {src,dst,type,norm}

// ---------------- K0: zero agg + counters + fused histogram --------------------
__global__ void zero_hist_kernel(const int* __restrict__ etype) {
    int i = blockIdx.x * blockDim.x + threadIdx.x;
    const int n4 = N_NODES * FEAT / 4;   // 640000
    if (i < n4) reinterpret_cast<float4*>(g_agg)[i] =
        make_float4(0.f, 0.f, 0.f, 0.f);
    if (i < NCNT) g_counts[i] = 0;
    __threadfence();                     // counters zeroed before any hist RED
    // grid-wide: counters zeroed by the first NCNT threads; ensure ordering by
    // doing histogram from a disjoint high range of threads (i >= n4 impossible)
    // -> safe approach: histogram in the SAME thread after fence only works
    //    within a thread. Use separate pass below instead.
}

__global__ void hist_kernel(const int* __restrict__ etype) {
    int e = blockIdx.x * blockDim.x + threadIdx.x;
    if (e < N_EDGES)
        atomicAdd(&g_counts[etype[e] * NSUB + (e & (NSUB - 1))], 1);
}

// ---------------- K2: exclusive scan over 7360 counters ------------------------
__global__ void __launch_bounds__(1024) scan_kernel() {
    __shared__ int sp[1024];
    int t = threadIdx.x;
    int base = t * 8;
    int v[8];
    int sum = 0;
    #pragma unroll
    for (int i = 0; i < 8; ++i) {
        v[i] = (base + i < NCNT) ? g_counts[base + i] : 0;
        sum += v[i];
    }
    sp[t] = sum;
    __syncthreads();
    #pragma unroll
    for (int off = 1; off < 1024; off <<= 1) {
        int x = (t >= off) ? sp[t - off] : 0;
        __syncthreads();
        sp[t] += x;
        __syncthreads();
    }
    int run = sp[t] - sum;
    #pragma unroll
    for (int i = 0; i < 8; ++i) {
        if (base + i < NCNT) g_cursor[base + i] = run;
        run += v[i];
    }
}

// ---------------- K3: scatter packed edge records -------------------------------
__global__ void scatter_kernel(const int* __restrict__ etype,
                               const int* __restrict__ esrc,
                               const int* __restrict__ edst,
                               const float* __restrict__ enorm) {
    int e = blockIdx.x * blockDim.x + threadIdx.x;
    if (e < N_EDGES) {
        int t = etype[e];
        int c = t * NSUB + (e & (NSUB - 1));
        int pos = atomicAdd(&g_cursor[c], 1);
        g_edge[pos] = make_int4(esrc[e], edst[e], t, __float_as_int(enorm[e]));
    }
}

// ---------------- K4: edge message + vector scatter-add -------------------------
// One warp per 32 sorted edges. Recs loaded coalesced (1 LDG.128/lane), then
// shfl-broadcast per edge. 2-edge software pipeline for MLP. lane -> 4 channels.
__global__ void __launch_bounds__(256) edge_kernel(
    const float* __restrict__ h,
    const float* __restrict__ weight)
{
    const int warp = blockIdx.x * 8 + (threadIdx.x >> 5);
    if (warp >= NWARPS) return;
    const int lane = threadIdx.x & 31;
    const int e0   = warp * EPW;
    const int b    = lane >> 2;
    const int q    = lane & 3;

    // coalesced: each lane owns one edge record of this warp's chunk
    int4 myrec = __ldg(&g_edge[e0 + lane]);

    unsigned long long w01[16], w23[16];
    int cur = -1;

    #pragma unroll 1
    for (int i = 0; i < EPW; i += 2) {
        int sA = __shfl_sync(0xffffffffu, myrec.x, i);
        int dA = __shfl_sync(0xffffffffu, myrec.y, i);
        int tA = __shfl_sync(0xffffffffu, myrec.z, i);
        int nA = __shfl_sync(0xffffffffu, myrec.w, i);
        int sB = __shfl_sync(0xffffffffu, myrec.x, i + 1);
        int dB = __shfl_sync(0xffffffffu, myrec.y, i + 1);
        int tB = __shfl_sync(0xffffffffu, myrec.z, i + 1);
        int nB = __shfl_sync(0xffffffffu, myrec.w, i + 1);

        // issue all h loads for both edges before any compute (MLP=8)
        const float4* pA = reinterpret_cast<const float4*>(
            h + (size_t)sA * FEAT + b * SI);
        const float4* pB = reinterpret_cast<const float4*>(
            h + (size_t)sB * FEAT + b * SI);
        float4 a0 = __ldg(pA + 0);
        float4 a1 = __ldg(pA + 1);
        float4 a2 = __ldg(pA + 2);
        float4 a3 = __ldg(pA + 3);
        float4 b0 = __ldg(pB + 0);
        float4 b1 = __ldg(pB + 1);
        float4 b2 = __ldg(pB + 2);
        float4 b3 = __ldg(pB + 3);

        if (tA != cur) {
            cur = tA;
            const float4* wp = reinterpret_cast<const float4*>(
                weight + (size_t)cur * WROW + b * (SI * SO)) + q;
            #pragma unroll
            for (int k = 0; k < 16; ++k) {
                float4 v = __ldg(wp + k * 4);
                PACK_F32X2(w01[k], v.x, v.y);
                PACK_F32X2(w23[k], v.z, v.w);
            }
        }
        {
            unsigned long long acc01 = 0ULL, acc23 = 0ULL;
            #define EK(i, val) { unsigned long long _p;              \
                PACK_F32X2(_p, val, val);                             \
                FMA_F32X2(acc01, _p, w01[i], acc01);                  \
                FMA_F32X2(acc23, _p, w23[i], acc23); }
            EK(0,a0.x) EK(1,a0.y) EK(2,a0.z) EK(3,a0.w)
            EK(4,a1.x) EK(5,a1.y) EK(6,a1.z) EK(7,a1.w)
            EK(8,a2.x) EK(9,a2.y) EK(10,a2.z) EK(11,a2.w)
            EK(12,a3.x) EK(13,a3.y) EK(14,a3.z) EK(15,a3.w)
            #undef EK
            float en = __int_as_float(nA);
            float r0, r1, r2, r3;
            UNPACK_F32X2(r0, r1, acc01);
            UNPACK_F32X2(r2, r3, acc23);
            r0 *= en; r1 *= en; r2 *= en; r3 *= en;
            float* dst = g_agg + (size_t)dA * FEAT + lane * 4;
            asm volatile("red.global.add.v4.f32 [%0], {%1, %2, %3, %4};"
                         :: "l"(dst), "f"(r0), "f"(r1), "f"(r2), "f"(r3)
                         : "memory");
        }

        if (tB != cur) {
            cur = tB;
            const float4* wp = reinterpret_cast<const float4*>(
                weight + (size_t)cur * WROW + b * (SI * SO)) + q;
            #pragma unroll
            for (int k = 0; k < 16; ++k) {
                float4 v = __ldg(wp + k * 4);
                PACK_F32X2(w01[k], v.x, v.y);
                PACK_F32X2(w23[k], v.z, v.w);
            }
        }
        {
            unsigned long long acc01 = 0ULL, acc23 = 0ULL;
            #define EK(i, val) { unsigned long long _p;              \
                PACK_F32X2(_p, val, val);                             \
                FMA_F32X2(acc01, _p, w01[i], acc01);                  \
                FMA_F32X2(acc23, _p, w23[i], acc23); }
            EK(0,b0.x) EK(1,b0.y) EK(2,b0.z) EK(3,b0.w)
            EK(4,b1.x) EK(5,b1.y) EK(6,b1.z) EK(7,b1.w)
            EK(8,b2.x) EK(9,b2.y) EK(10,b2.z) EK(11,b2.w)
            EK(12,b3.x) EK(13,b3.y) EK(14,b3.z) EK(15,b3.w)
            #undef EK
            float en = __int_as_float(nB);
            float r0, r1, r2, r3;
            UNPACK_F32X2(r0, r1, acc01);
            UNPACK_F32X2(r2, r3, acc23);
            r0 *= en; r1 *= en; r2 *= en; r3 *= en;
            float* dst = g_agg + (size_t)dB * FEAT + lane * 4;
            asm volatile("red.global.add.v4.f32 [%0], {%1, %2, %3, %4};"
                         :: "l"(dst), "f"(r0), "f"(r1), "f"(r2), "f"(r3)
                         : "memory");
        }
    }
}

// ---------------- K5: self-loop GEMM + epilogue + time-embedding ---------------
#define MT 64
#define KT 32
__global__ void __launch_bounds__(256) final_kernel(
    const float* __restrict__ h,
    const float* __restrict__ node_norm,
    const float* __restrict__ h_bias,
    const float* __restrict__ loop_weight,
    const float* __restrict__ time_embed,
    const int*   __restrict__ time_idx,
    float*       __restrict__ out)
{
    __shared__ float sW[KT][FEAT];
    __shared__ float sH[MT][KT + 1];

    const int tid = threadIdx.x;
    const int tm  = tid >> 5;
    const int to  = tid & 31;
    const int n0  = blockIdx.x * MT;

    unsigned long long acc01[8], acc23[8];
    #pragma unroll
    for (int r = 0; r < 8; ++r) { acc01[r] = 0ULL; acc23[r] = 0ULL; }

    for (int kt = 0; kt < FEAT / KT; ++kt) {
        #pragma unroll
        for (int j = 0; j < 4; ++j) {
            int idx = tid + j * 256;
            int r   = idx >> 5;
            int c4  = idx & 31;
            float4 v = __ldg(reinterpret_cast<const float4*>(
                loop_weight + (size_t)(kt * KT + r) * FEAT + c4 * 4));
            *reinterpret_cast<float4*>(&sW[r][c4 * 4]) = v;
        }
        #pragma unroll
        for (int j = 0; j < 2; ++j) {
            int idx = tid + j * 256;
            int r   = idx >> 3;
            int c4  = idx & 7;
            int n   = n0 + r;
            float4 v = make_float4(0.f, 0.f, 0.f, 0.f);
            if (n < N_NODES)
                v = __ldg(reinterpret_cast<const float4*>(
                        h + (size_t)n * FEAT + kt * KT + c4 * 4));
            sH[r][c4 * 4 + 0] = v.x;
            sH[r][c4 * 4 + 1] = v.y;
            sH[r][c4 * 4 + 2] = v.z;
            sH[r][c4 * 4 + 3] = v.w;
        }
        __syncthreads();

        #pragma unroll
        for (int k = 0; k < KT; ++k) {
            float4 wv = *reinterpret_cast<const float4*>(&sW[k][to * 4]);
            unsigned long long w01, w23;
            PACK_F32X2(w01, wv.x, wv.y);
            PACK_F32X2(w23, wv.z, wv.w);
            #pragma unroll
            for (int r = 0; r < 8; ++r) {
                float hv = sH[tm * 8 + r][k];
                unsigned long long h2;
                PACK_F32X2(h2, hv, hv);
                FMA_F32X2(acc01[r], h2, w01, acc01[r]);
                FMA_F32X2(acc23[r], h2, w23, acc23[r]);
            }
        }
        __syncthreads();
    }

    const int o0 = to * 4;
    float4 hb = __ldg(reinterpret_cast<const float4*>(h_bias + o0));
    #pragma unroll
    for (int r = 0; r < 8; ++r) {
        int n = n0 + tm * 8 + r;
        if (n < N_NODES) {
            float nn = __ldg(&node_norm[n]);
            float4 ag = *reinterpret_cast<const float4*>(&g_agg[(size_t)n * FEAT + o0]);
            float a0, a1, a2, a3;
            UNPACK_F32X2(a0, a1, acc01[r]);
            UNPACK_F32X2(a2, a3, acc23[r]);
            float4 res;
            res.x = fmaxf(a0 + ag.x * nn + hb.x, 0.f);
            res.y = fmaxf(a1 + ag.y * nn + hb.y, 0.f);
            res.z = fmaxf(a2 + ag.z * nn + hb.z, 0.f);
            res.w = fmaxf(a3 + ag.w * nn + hb.w, 0.f);
            *reinterpret_cast<float4*>(out + (size_t)n * FEAT + o0) = res;
        }
    }

    float* out2 = out + (size_t)N_NODES * FEAT;
    #pragma unroll
    for (int j = 0; j < 8; ++j) {
        int idx = tid + j * 256;
        int r   = idx >> 5;
        int c4  = idx & 31;
        int n   = n0 + r;
        if (n < N_NODES) {
            int ti = __ldg(&time_idx[n]);
            float4 v = __ldg(reinterpret_cast<const float4*>(
                time_embed + (size_t)ti * FEAT + c4 * 4));
            *reinterpret_cast<float4*>(out2 + (size_t)n * FEAT + c4 * 4) = v;
        }
    }
}

// ---------------- launch ---------------------------------------------------------
extern "C" void kernel_launch(void* const* d_in, const int* in_sizes, int n_in,
                              void* d_out, int out_size) {
    const float* h           = (const float*)d_in[0];
    const float* edge_norm   = (const float*)d_in[1];
    const float* node_norm   = (const float*)d_in[2];
    const float* weight      = (const float*)d_in[3];
    const float* h_bias      = (const float*)d_in[4];
    const float* loop_weight = (const float*)d_in[5];
    const float* time_embed  = (const float*)d_in[6];
    const int*   edge_src    = (const int*)d_in[7];
    const int*   edge_dst    = (const int*)d_in[8];
    const int*   edge_type   = (const int*)d_in[9];
    const int*   time_idx    = (const int*)d_in[10];
    float* out = (float*)d_out;

    {
        int n4 = N_NODES * FEAT / 4;
        zero_hist_kernel<<<(n4 + 255) / 256, 256>>>(edge_type);
    }
    hist_kernel<<<(N_EDGES + 255) / 256, 256>>>(edge_type);
    scan_kernel<<<1, 1024>>>();
    scatter_kernel<<<(N_EDGES + 255) / 256, 256>>>(edge_type, edge_src,
                                                   edge_dst, edge_norm);
    {
        int ctas = (NWARPS + 7) / 8;     // 782
        edge_kernel<<<ctas, 256>>>(h, weight);
    }
    final_kernel<<<(N_NODES + MT - 1) / MT, 256>>>(
        h, node_norm, h_bias, loop_weight, time_embed, time_idx, out);
}

// round 4
// speedup vs baseline: 1.0208x; 1.0208x over previous
#include <cuda_runtime.h>
#include <cuda_bf16.h>
#include <cstdint>

#define N_NODES 20000
#define N_EDGES 200000
#define FEAT    128
#define NB      8
#define SI      16
#define SO      16
#define NREL    230
#define WROW    (NB*SI*SO)       // 2048 floats per relation
#define NSUB    32               // sub-counters per relation
#define NCNT    (NREL*NSUB)      // 7360
#define EPW     32               // edges per warp (200000/32 = 6250 exact)
#define NWARPS  (N_EDGES/EPW)

// ---------------- packed f32x2 helpers (Blackwell sm_103a) --------------------
#define PACK_F32X2(out, lo, hi) \
    asm("mov.b64 %0, {%1, %2};" : "=l"(out) : "f"(lo), "f"(hi))
#define UNPACK_F32X2(lo, hi, in) \
    asm("mov.b64 {%0, %1}, %2;" : "=f"(lo), "=f"(hi) : "l"(in))
#define FMA_F32X2(d, a, b, c) \
    asm("fma.rn.f32x2 %0, %1, %2, %3;" : "=l"(d) : "l"(a), "l"(b), "l"(c))

// ---------------- scratch (device globals) -------------------------------------
__device__ float g_agg[(size_t)N_NODES * FEAT];      // 10.24 MB
__device__ int   g_counts[NCNT];                     // static-zero at load; re-zeroed by scan
__device__ int   g_cursor[NCNT];
__device__ int4  g_edge[N_EDGES];                    // sorted {src,dst,type,norm}

// ---------------- K0: zero agg + fused histogram (disjoint data) ---------------
// g_counts is guaranteed zero on entry: zero-init at module load, and scan_kernel
// re-zeroes it after consuming, so every graph replay starts clean.
__global__ void zero_hist_kernel(const int* __restrict__ etype) {
    int i = blockIdx.x * blockDim.x + threadIdx.x;
    const int n4 = N_NODES * FEAT / 4;   // 640000
    if (i < n4) reinterpret_cast<float4*>(g_agg)[i] =
        make_float4(0.f, 0.f, 0.f, 0.f);
    if (i < N_EDGES)
        atomicAdd(&g_counts[etype[i] * NSUB + (i & (NSUB - 1))], 1);  // RED
}

// ---------------- K1: exclusive scan over 7360 counters + reset ----------------
__global__ void __launch_bounds__(1024) scan_kernel() {
    __shared__ int sp[1024];
    int t = threadIdx.x;
    int base = t * 8;
    int v[8];
    int sum = 0;
    #pragma unroll
    for (int i = 0; i < 8; ++i) {
        if (base + i < NCNT) {
            v[i] = g_counts[base + i];
            g_counts[base + i] = 0;          // reset for next replay
        } else v[i] = 0;
        sum += v[i];
    }
    sp[t] = sum;
    __syncthreads();
    #pragma unroll
    for (int off = 1; off < 1024; off <<= 1) {
        int x = (t >= off) ? sp[t - off] : 0;
        __syncthreads();
        sp[t] += x;
        __syncthreads();
    }
    int run = sp[t] - sum;
    #pragma unroll
    for (int i = 0; i < 8; ++i) {
        if (base + i < NCNT) g_cursor[base + i] = run;
        run += v[i];
    }
}

// ---------------- K2: scatter packed edge records -------------------------------
__global__ void scatter_kernel(const int* __restrict__ etype,
                               const int* __restrict__ esrc,
                               const int* __restrict__ edst,
                               const float* __restrict__ enorm) {
    int e = blockIdx.x * blockDim.x + threadIdx.x;
    if (e < N_EDGES) {
        int t = etype[e];
        int c = t * NSUB + (e & (NSUB - 1));
        int pos = atomicAdd(&g_cursor[c], 1);
        g_edge[pos] = make_int4(esrc[e], edst[e], t, __float_as_int(enorm[e]));
    }
}

// ---------------- K3: edge message + vector scatter-add -------------------------
// Warp per 32 sorted edges; lane -> 4 output channels (b = lane>>2, q = lane&3).
// 1-deep prefetch pipeline: rec[e+1] and h[rec[e+1]] load behind current compute.
__global__ void __launch_bounds__(256) edge_kernel(
    const float* __restrict__ h,
    const float* __restrict__ weight)
{
    const int warp = blockIdx.x * 8 + (threadIdx.x >> 5);
    if (warp >= NWARPS) return;
    const int lane = threadIdx.x & 31;
    const int e0   = warp * EPW;
    const int b    = lane >> 2;
    const int q    = lane & 3;

    unsigned long long w01[16], w23[16];
    int cur = -1;

    // prologue: load first rec + its h row
    int4 rec = __ldg(&g_edge[e0]);
    const float4* hp = reinterpret_cast<const float4*>(
        h + (size_t)rec.x * FEAT + b * SI);
    float4 x0 = __ldg(hp + 0);
    float4 x1 = __ldg(hp + 1);
    float4 x2 = __ldg(hp + 2);
    float4 x3 = __ldg(hp + 3);

    #pragma unroll 1
    for (int i = 0; i < EPW; ++i) {
        // prefetch next record (issues early, consumed after compute)
        int4 nrec = rec;
        if (i + 1 < EPW) nrec = __ldg(&g_edge[e0 + i + 1]);

        // weights for current edge's relation (rare reload; sorted by type)
        if (rec.z != cur) {
            cur = rec.z;
            const char* wbase = reinterpret_cast<const char*>(
                weight + (size_t)cur * WROW + b * (SI * SO) + q * 4);
            #pragma unroll
            for (int k = 0; k < 16; ++k) {
                ulonglong2 wv = __ldg(reinterpret_cast<const ulonglong2*>(
                    wbase + k * (SO * 4)));
                w01[k] = wv.x;
                w23[k] = wv.y;
            }
        }

        // compute message for current edge
        unsigned long long a01 = 0ULL, a23 = 0ULL;
        #define EK(k, val) { unsigned long long _p;              \
            PACK_F32X2(_p, val, val);                             \
            FMA_F32X2(a01, _p, w01[k], a01);                      \
            FMA_F32X2(a23, _p, w23[k], a23); }
        EK(0,x0.x) EK(1,x0.y) EK(2,x0.z) EK(3,x0.w)
        EK(4,x1.x) EK(5,x1.y) EK(6,x1.z) EK(7,x1.w)
        EK(8,x2.x) EK(9,x2.y) EK(10,x2.z) EK(11,x2.w)
        EK(12,x3.x) EK(13,x3.y) EK(14,x3.z) EK(15,x3.w)
        #undef EK

        float en = __int_as_float(rec.w);
        float r0, r1, r2, r3;
        UNPACK_F32X2(r0, r1, a01);
        UNPACK_F32X2(r2, r3, a23);
        r0 *= en; r1 *= en; r2 *= en; r3 *= en;
        float* dst = g_agg + (size_t)rec.y * FEAT + lane * 4;
        asm volatile("red.global.add.v4.f32 [%0], {%1, %2, %3, %4};"
                     :: "l"(dst), "f"(r0), "f"(r1), "f"(r2), "f"(r3)
                     : "memory");

        // prefetch next edge's h row (overlaps with next iter's weight check)
        if (i + 1 < EPW) {
            const float4* np = reinterpret_cast<const float4*>(
                h + (size_t)nrec.x * FEAT + b * SI);
            x0 = __ldg(np + 0);
            x1 = __ldg(np + 1);
            x2 = __ldg(np + 2);
            x3 = __ldg(np + 3);
        }
        rec = nrec;
    }
}

// ---------------- K4: self-loop GEMM + epilogue + time-embedding ---------------
#define MT 64
#define KT 32
__global__ void __launch_bounds__(256) final_kernel(
    const float* __restrict__ h,
    const float* __restrict__ node_norm,
    const float* __restrict__ h_bias,
    const float* __restrict__ loop_weight,
    const float* __restrict__ time_embed,
    const int*   __restrict__ time_idx,
    float*       __restrict__ out)
{
    __shared__ float sW[KT][FEAT];           // 16 KB
    __shared__ float sH[MT][KT + 4];         // row stride 144B (16B aligned)

    const int tid = threadIdx.x;
    const int tm  = tid >> 5;
    const int to  = tid & 31;
    const int n0  = blockIdx.x * MT;

    unsigned long long acc01[8], acc23[8];
    #pragma unroll
    for (int r = 0; r < 8; ++r) { acc01[r] = 0ULL; acc23[r] = 0ULL; }

    for (int kt = 0; kt < FEAT / KT; ++kt) {
        #pragma unroll
        for (int j = 0; j < 4; ++j) {
            int idx = tid + j * 256;
            int r   = idx >> 5;
            int c4  = idx & 31;
            float4 v = __ldg(reinterpret_cast<const float4*>(
                loop_weight + (size_t)(kt * KT + r) * FEAT + c4 * 4));
            *reinterpret_cast<float4*>(&sW[r][c4 * 4]) = v;
        }
        #pragma unroll
        for (int j = 0; j < 2; ++j) {
            int idx = tid + j * 256;
            int r   = idx >> 3;
            int c4  = idx & 7;
            int n   = n0 + r;
            float4 v = make_float4(0.f, 0.f, 0.f, 0.f);
            if (n < N_NODES)
                v = __ldg(reinterpret_cast<const float4*>(
                        h + (size_t)n * FEAT + kt * KT + c4 * 4));
            *reinterpret_cast<float4*>(&sH[r][c4 * 4]) = v;
        }
        __syncthreads();

        #pragma unroll
        for (int k = 0; k < KT; k += 4) {
            // 4 k-steps of weights for this thread's 4 columns (no packing needed)
            ulonglong2 wv0 = *reinterpret_cast<const ulonglong2*>(&sW[k + 0][to * 4]);
            ulonglong2 wv1 = *reinterpret_cast<const ulonglong2*>(&sW[k + 1][to * 4]);
            ulonglong2 wv2 = *reinterpret_cast<const ulonglong2*>(&sW[k + 2][to * 4]);
            ulonglong2 wv3 = *reinterpret_cast<const ulonglong2*>(&sW[k + 3][to * 4]);
            #pragma unroll
            for (int r = 0; r < 8; ++r) {
                float4 hv = *reinterpret_cast<const float4*>(&sH[tm * 8 + r][k]);
                unsigned long long h2;
                PACK_F32X2(h2, hv.x, hv.x);
                FMA_F32X2(acc01[r], h2, wv0.x, acc01[r]);
                FMA_F32X2(acc23[r], h2, wv0.y, acc23[r]);
                PACK_F32X2(h2, hv.y, hv.y);
                FMA_F32X2(acc01[r], h2, wv1.x, acc01[r]);
                FMA_F32X2(acc23[r], h2, wv1.y, acc23[r]);
                PACK_F32X2(h2, hv.z, hv.z);
                FMA_F32X2(acc01[r], h2, wv2.x, acc01[r]);
                FMA_F32X2(acc23[r], h2, wv2.y, acc23[r]);
                PACK_F32X2(h2, hv.w, hv.w);
                FMA_F32X2(acc01[r], h2, wv3.x, acc01[r]);
                FMA_F32X2(acc23[r], h2, wv3.y, acc23[r]);
            }
        }
        __syncthreads();
    }

    // epilogue: relu(agg*node_norm + h_bias + loop_message)
    const int o0 = to * 4;
    float4 hb = __ldg(reinterpret_cast<const float4*>(h_bias + o0));
    #pragma unroll
    for (int r = 0; r < 8; ++r) {
        int n = n0 + tm * 8 + r;
        if (n < N_NODES) {
            float nn = __ldg(&node_norm[n]);
            float4 ag = *reinterpret_cast<const float4*>(&g_agg[(size_t)n * FEAT + o0]);
            float a0, a1, a2, a3;
            UNPACK_F32X2(a0, a1, acc01[r]);
            UNPACK_F32X2(a2, a3, acc23[r]);
            float4 res;
            res.x = fmaxf(a0 + ag.x * nn + hb.x, 0.f);
            res.y = fmaxf(a1 + ag.y * nn + hb.y, 0.f);
            res.z = fmaxf(a2 + ag.z * nn + hb.z, 0.f);
            res.w = fmaxf(a3 + ag.w * nn + hb.w, 0.f);
            *reinterpret_cast<float4*>(out + (size_t)n * FEAT + o0) = res;
        }
    }

    // time embedding gather
    float* out2 = out + (size_t)N_NODES * FEAT;
    #pragma unroll
    for (int j = 0; j < 8; ++j) {
        int idx = tid + j * 256;
        int r   = idx >> 5;
        int c4  = idx & 31;
        int n   = n0 + r;
        if (n < N_NODES) {
            int ti = __ldg(&time_idx[n]);
            float4 v = __ldg(reinterpret_cast<const float4*>(
                time_embed + (size_t)ti * FEAT + c4 * 4));
            *reinterpret_cast<float4*>(out2 + (size_t)n * FEAT + c4 * 4) = v;
        }
    }
}

// ---------------- launch ---------------------------------------------------------
extern "C" void kernel_launch(void* const* d_in, const int* in_sizes, int n_in,
                              void* d_out, int out_size) {
    const float* h           = (const float*)d_in[0];
    const float* edge_norm   = (const float*)d_in[1];
    const float* node_norm   = (const float*)d_in[2];
    const float* weight      = (const float*)d_in[3];
    const float* h_bias      = (const float*)d_in[4];
    const float* loop_weight = (const float*)d_in[5];
    const float* time_embed  = (const float*)d_in[6];
    const int*   edge_src    = (const int*)d_in[7];
    const int*   edge_dst    = (const int*)d_in[8];
    const int*   edge_type   = (const int*)d_in[9];
    const int*   time_idx    = (const int*)d_in[10];
    float* out = (float*)d_out;

    {
        int n4 = N_NODES * FEAT / 4;     // 640000 threads covers both tasks
        zero_hist_kernel<<<(n4 + 255) / 256, 256>>>(edge_type);
    }
    scan_kernel<<<1, 1024>>>();
    scatter_kernel<<<(N_EDGES + 255) / 256, 256>>>(edge_type, edge_src,
                                                   edge_dst, edge_norm);
    {
        int ctas = (NWARPS + 7) / 8;     // 782
        edge_kernel<<<ctas, 256>>>(h, weight);
    }
    final_kernel<<<(N_NODES + MT - 1) / MT, 256>>>(
        h, node_norm, h_bias, loop_weight, time_embed, time_idx, out);
}